// round 3
// baseline (speedup 1.0000x reference)
#include <cuda_runtime.h>
#include <math.h>

#define B_ 64
#define H_ 512
#define V_ 32000
#define T_ 32
#define NTILES 500   // V_/64

// ---------------- persistent state (device globals; no allocation) ----------------
__device__ float g_h[B_ * H_];
__device__ float g_c[B_ * H_];
__device__ float g_gates_part[4 * B_ * 2048];   // 4 K-chunks of partial gates
__device__ float g_amax_val[NTILES * B_];
__device__ int   g_amax_idx[NTILES * B_];
__device__ int   g_tok[B_];

__device__ __forceinline__ float sigmoidf_(float x) { return 1.0f / (1.0f + expf(-x)); }

// ---------------- init: h = c = features; tok = captions[:,0] ----------------
// captions may be int64 or int32 depending on JAX x64 config; detect by content.
__global__ void init_kernel(const float* __restrict__ features,
                            const void* __restrict__ captions) {
    int b = blockIdx.x, col = threadIdx.x;
    float v = features[b * H_ + col];
    g_h[b * H_ + col] = v;
    g_c[b * H_ + col] = v;
    if (b == 0) {
        __shared__ int is64;
        if (col == 0) {
            // If the buffer holds int64 tokens (<32000), every odd int32 word is 0.
            // Check 16 odd words (stays in-bounds even if data is int32: 64 words).
            const int* c32 = (const int*)captions;
            int ornz = 0;
            for (int q = 0; q < 16; ++q) ornz |= c32[2 * q + 1];
            is64 = (ornz == 0) ? 1 : 0;
        }
        __syncthreads();
        if (col < B_) {
            int tk;
            if (is64) tk = (int)((const long long*)captions)[col];
            else      tk = ((const int*)captions)[col];
            g_tok[col] = tk;
        }
    }
}

// ---------------- LSTM gates GEMM (partials), grid (64 colgroups, 4 K-chunks) ----
// chunk 0,1: x @ W_ih^T halves (x = embed_W[tok]);  chunk 2,3: h @ W_hh^T halves.
__global__ void __launch_bounds__(256) cell_kernel(const float* __restrict__ embedW,
                                                   const float* __restrict__ W_ih,
                                                   const float* __restrict__ W_hh) {
    __shared__ float Ws[32][32];   // [k][n]
    __shared__ float Xs[32][64];   // [k][m]
    int cg  = blockIdx.x;          // 0..63 -> 32 gate columns each
    int kc  = blockIdx.y;          // 0..3  -> K-chunk of 256
    int tid = threadIdx.x;
    int gbase = cg * 32;
    int koff  = (kc & 1) * 256;
    const float* Wmat = (kc < 2) ? W_ih : W_hh;

    int wn = tid & 31;
    int wk = (tid >> 5) << 2;      // 0..28
    const float* wptr = Wmat + (size_t)(gbase + wn) * H_ + koff + wk;

    int xm = tid & 63;
    int xk = (tid >> 6) << 3;      // 0,8,16,24
    const float* xrow;
    if (kc < 2) xrow = embedW + (size_t)g_tok[xm] * H_ + koff + xk;
    else        xrow = g_h    + (size_t)xm        * H_ + koff + xk;

    int nt = (tid & 15) * 2;
    int mt = (tid >> 4) * 4;
    float acc[4][2] = {};

    for (int s = 0; s < 8; ++s) {
        float4 wv = *(const float4*)(wptr + s * 32);
        float4 x0 = *(const float4*)(xrow + s * 32);
        float4 x1 = *(const float4*)(xrow + s * 32 + 4);
        __syncthreads();
        Ws[wk + 0][wn] = wv.x; Ws[wk + 1][wn] = wv.y;
        Ws[wk + 2][wn] = wv.z; Ws[wk + 3][wn] = wv.w;
        Xs[xk + 0][xm] = x0.x; Xs[xk + 1][xm] = x0.y;
        Xs[xk + 2][xm] = x0.z; Xs[xk + 3][xm] = x0.w;
        Xs[xk + 4][xm] = x1.x; Xs[xk + 5][xm] = x1.y;
        Xs[xk + 6][xm] = x1.z; Xs[xk + 7][xm] = x1.w;
        __syncthreads();
#pragma unroll
        for (int k = 0; k < 32; ++k) {
            float a0 = Ws[k][nt], a1 = Ws[k][nt + 1];
            float4 b = *(const float4*)&Xs[k][mt];
            acc[0][0] += b.x * a0; acc[0][1] += b.x * a1;
            acc[1][0] += b.y * a0; acc[1][1] += b.y * a1;
            acc[2][0] += b.z * a0; acc[2][1] += b.z * a1;
            acc[3][0] += b.w * a0; acc[3][1] += b.w * a1;
        }
    }
    float* gp = g_gates_part + (size_t)kc * (B_ * 2048);
#pragma unroll
    for (int i = 0; i < 4; ++i)
#pragma unroll
        for (int j = 0; j < 2; ++j)
            gp[(size_t)(mt + i) * 2048 + gbase + nt + j] = acc[i][j];
}

// ---------------- activations + cell/hidden update ----------------
__global__ void update_kernel(const float* __restrict__ b_ih,
                              const float* __restrict__ b_hh) {
    int b = blockIdx.x, col = threadIdx.x;   // 64 x 512
    float gi = b_ih[col]        + b_hh[col];
    float gf = b_ih[col + 512]  + b_hh[col + 512];
    float gg = b_ih[col + 1024] + b_hh[col + 1024];
    float go = b_ih[col + 1536] + b_hh[col + 1536];
#pragma unroll
    for (int ks = 0; ks < 4; ++ks) {
        const float* p = g_gates_part + (size_t)ks * (B_ * 2048) + (size_t)b * 2048;
        gi += p[col]; gf += p[col + 512]; gg += p[col + 1024]; go += p[col + 1536];
    }
    float i = sigmoidf_(gi), f = sigmoidf_(gf), g = tanhf(gg), o = sigmoidf_(go);
    float c = f * g_c[b * H_ + col] + i * g;
    float h = o * tanhf(c);
    g_c[b * H_ + col] = c;
    g_h[b * H_ + col] = h;
}

// ---------------- logits GEMM: out[:,t,:] = h @ lin_W^T + lin_b, + argmax partials
// 500 blocks; tile 64 W-rows x 64 batch x K=512; double-buffered smem; 4x4/thread.
__global__ void __launch_bounds__(256) logits_kernel(const float* __restrict__ W,
                                                     const float* __restrict__ bias,
                                                     float* __restrict__ out, int t) {
    __shared__ float Ws[2][16][64];
    __shared__ float Hs[2][16][64];
    __shared__ float rv[64][16];
    __shared__ int   ri[64][16];
    int tile = blockIdx.x;
    int n0   = tile * 64;
    int tid  = threadIdx.x;
    int ln = tid & 63;
    int lk = (tid >> 6) << 2;       // 0,4,8,12
    const float* wp = W   + (size_t)(n0 + ln) * H_ + lk;
    const float* hp = g_h + (size_t)ln * H_ + lk;
    int nt = (tid & 15) * 4;
    int mt = (tid >> 4) * 4;
    float acc[4][4] = {};

    float4 wv = *(const float4*)wp;
    float4 hv = *(const float4*)hp;
    Ws[0][lk + 0][ln] = wv.x; Ws[0][lk + 1][ln] = wv.y;
    Ws[0][lk + 2][ln] = wv.z; Ws[0][lk + 3][ln] = wv.w;
    Hs[0][lk + 0][ln] = hv.x; Hs[0][lk + 1][ln] = hv.y;
    Hs[0][lk + 2][ln] = hv.z; Hs[0][lk + 3][ln] = hv.w;
    __syncthreads();
    int buf = 0;
    for (int s = 0; s < 32; ++s) {
        if (s < 31) {
            wv = *(const float4*)(wp + (s + 1) * 16);
            hv = *(const float4*)(hp + (s + 1) * 16);
        }
#pragma unroll
        for (int k = 0; k < 16; ++k) {
            float4 a  = *(const float4*)&Ws[buf][k][nt];
            float4 bb = *(const float4*)&Hs[buf][k][mt];
            acc[0][0] += bb.x * a.x; acc[0][1] += bb.x * a.y; acc[0][2] += bb.x * a.z; acc[0][3] += bb.x * a.w;
            acc[1][0] += bb.y * a.x; acc[1][1] += bb.y * a.y; acc[1][2] += bb.y * a.z; acc[1][3] += bb.y * a.w;
            acc[2][0] += bb.z * a.x; acc[2][1] += bb.z * a.y; acc[2][2] += bb.z * a.z; acc[2][3] += bb.z * a.w;
            acc[3][0] += bb.w * a.x; acc[3][1] += bb.w * a.y; acc[3][2] += bb.w * a.z; acc[3][3] += bb.w * a.w;
        }
        if (s < 31) {
            int nb = buf ^ 1;
            Ws[nb][lk + 0][ln] = wv.x; Ws[nb][lk + 1][ln] = wv.y;
            Ws[nb][lk + 2][ln] = wv.z; Ws[nb][lk + 3][ln] = wv.w;
            Hs[nb][lk + 0][ln] = hv.x; Hs[nb][lk + 1][ln] = hv.y;
            Hs[nb][lk + 2][ln] = hv.z; Hs[nb][lk + 3][ln] = hv.w;
            __syncthreads();
            buf = nb;
        }
    }
    // epilogue: bias, store, per-tile argmax partial
    float4 bv4 = *(const float4*)(bias + n0 + nt);
#pragma unroll
    for (int i2 = 0; i2 < 4; ++i2) {
        float4 o;
        o.x = acc[i2][0] + bv4.x;
        o.y = acc[i2][1] + bv4.y;
        o.z = acc[i2][2] + bv4.z;
        o.w = acc[i2][3] + bv4.w;
        int m = mt + i2;
        *(float4*)(out + (size_t)m * ((size_t)T_ * V_) + (size_t)t * V_ + n0 + nt) = o;
        float best = o.x; int bidx = n0 + nt;
        if (o.y > best) { best = o.y; bidx = n0 + nt + 1; }
        if (o.z > best) { best = o.z; bidx = n0 + nt + 2; }
        if (o.w > best) { best = o.w; bidx = n0 + nt + 3; }
        rv[m][tid & 15] = best;
        ri[m][tid & 15] = bidx;
    }
    __syncthreads();
    if (tid < 64) {
        float best = rv[tid][0]; int bidx = ri[tid][0];
#pragma unroll
        for (int j = 1; j < 16; ++j) {
            float v = rv[tid][j]; int id = ri[tid][j];
            if (v > best || (v == best && id < bidx)) { best = v; bidx = id; }
        }
        g_amax_val[tile * B_ + tid] = best;
        g_amax_idx[tile * B_ + tid] = bidx;
    }
}

// ---------------- final argmax over tile partials -> next token ----------------
__global__ void argmax_kernel() {
    int tid = threadIdx.x;   // 512
    int row = tid >> 3;      // 64 batch rows
    int j   = tid & 7;       // 8 lanes per row
    float bv = -3.4e38f; int bi = 0x7fffffff;
    for (int p = j; p < NTILES; p += 8) {
        float v = g_amax_val[p * B_ + row];
        int  id = g_amax_idx[p * B_ + row];
        if (v > bv || (v == bv && id < bi)) { bv = v; bi = id; }
    }
    for (int off = 4; off > 0; off >>= 1) {
        float ov = __shfl_down_sync(0xffffffffu, bv, off, 8);
        int   oi = __shfl_down_sync(0xffffffffu, bi, off, 8);
        if (ov > bv || (ov == bv && oi < bi)) { bv = ov; bi = oi; }
    }
    if (j == 0) g_tok[row] = bi;
}

// ---------------- launcher ----------------
extern "C" void kernel_launch(void* const* d_in, const int* in_sizes, int n_in,
                              void* d_out, int out_size) {
    // Identify inputs by element count (robust to the scalar 'lengths' slot):
    // features 32768 | captions 64 | embed_W 16384000 (1st) | W_ih 1048576 (1st)
    // W_hh 1048576 (2nd) | b_ih 2048 (1st) | b_hh 2048 (2nd) | lin_W 16384000 (2nd)
    // lin_b 32000
    const float *features = nullptr, *embedW = nullptr, *W_ih = nullptr, *W_hh = nullptr;
    const float *b_ih = nullptr, *b_hh = nullptr, *linW = nullptr, *linb = nullptr;
    const void  *captions = nullptr;
    for (int i = 0; i < n_in; ++i) {
        int s = in_sizes[i];
        const void* p = d_in[i];
        if (s == 32768)            features = (const float*)p;
        else if (s == 64)          captions = p;
        else if (s == 16384000) {  if (!embedW) embedW = (const float*)p; else linW = (const float*)p; }
        else if (s == 1048576)  {  if (!W_ih)   W_ih   = (const float*)p; else W_hh = (const float*)p; }
        else if (s == 2048)     {  if (!b_ih)   b_ih   = (const float*)p; else b_hh = (const float*)p; }
        else if (s == 32000)       linb = (const float*)p;
        // s == 1 (lengths) ignored; T_=32 is compile-time
    }
    float* out = (float*)d_out;

    init_kernel<<<B_, H_>>>(features, captions);
    for (int t = 0; t < T_; ++t) {
        cell_kernel<<<dim3(64, 4), 256>>>(embedW, W_ih, W_hh);
        update_kernel<<<B_, H_>>>(b_ih, b_hh);
        logits_kernel<<<NTILES, 256>>>(linW, linb, out, t);
        if (t < T_ - 1) argmax_kernel<<<1, 512>>>();
    }
}

// round 9
// speedup vs baseline: 1.4372x; 1.4372x over previous
#include <cuda_runtime.h>
#include <cuda_bf16.h>
#include <math.h>
#include <stdint.h>

#define B_ 64
#define H_ 512
#define V_ 32000
#define T_ 32
#define NBLOCKS 125         // 125 blocks x 256 vocab rows
#define NTILES 125

// ---------------- persistent state (device globals; no allocation) ----------------
__device__ float g_h[B_ * H_];
__device__ float g_c[B_ * H_];
__device__ __nv_bfloat16 g_Hhi[B_ * H_];
__device__ __nv_bfloat16 g_Hlo[B_ * H_];
__device__ __nv_bfloat16 g_Whi[V_ * H_];
__device__ __nv_bfloat16 g_Wlo[V_ * H_];
__device__ float g_gates_part[4 * B_ * 2048];
__device__ float g_amax_val[NTILES * B_];
__device__ int   g_amax_idx[NTILES * B_];
__device__ int   g_tok[B_];

__device__ __forceinline__ float sigmoidf_(float x) { return 1.0f / (1.0f + expf(-x)); }

// m16n8k16 row.col bf16 -> fp32 HMMA (baseline PTX, works on sm_103 target)
__device__ __forceinline__ void mma16816(float* d, const uint32_t* a, const uint32_t* b) {
    asm volatile("mma.sync.aligned.m16n8k16.row.col.f32.bf16.bf16.f32 "
                 "{%0,%1,%2,%3}, {%4,%5,%6,%7}, {%8,%9}, {%0,%1,%2,%3};"
                 : "+f"(d[0]), "+f"(d[1]), "+f"(d[2]), "+f"(d[3])
                 : "r"(a[0]), "r"(a[1]), "r"(a[2]), "r"(a[3]), "r"(b[0]), "r"(b[1]));
}

// ---------------- init: h = c = features; tok = captions[:,0] ----------------
__global__ void init_kernel(const float* __restrict__ features,
                            const void* __restrict__ captions) {
    int b = blockIdx.x, col = threadIdx.x;
    float v = features[b * H_ + col];
    g_h[b * H_ + col] = v;
    g_c[b * H_ + col] = v;
    __nv_bfloat16 hi = __float2bfloat16_rn(v);
    g_Hhi[b * H_ + col] = hi;
    g_Hlo[b * H_ + col] = __float2bfloat16_rn(v - __bfloat162float(hi));
    if (b == 0) {
        __shared__ int is64;
        if (col == 0) {
            const int* c32 = (const int*)captions;
            int ornz = 0;
            for (int q = 0; q < 16; ++q) ornz |= c32[2 * q + 1];
            is64 = (ornz == 0) ? 1 : 0;
        }
        __syncthreads();
        if (col < B_) {
            int tk;
            if (is64) tk = (int)((const long long*)captions)[col];
            else      tk = ((const int*)captions)[col];
            g_tok[col] = tk;
        }
    }
}

// ---------------- per-launch W -> bf16 hi/lo conversion ----------------
__global__ void convert_w_kernel(const float* __restrict__ W) {
    int i = (blockIdx.x * 256 + threadIdx.x) * 4;
    float4 v = *(const float4*)(W + i);
    __nv_bfloat16 h0 = __float2bfloat16_rn(v.x);
    __nv_bfloat16 h1 = __float2bfloat16_rn(v.y);
    __nv_bfloat16 h2 = __float2bfloat16_rn(v.z);
    __nv_bfloat16 h3 = __float2bfloat16_rn(v.w);
    __nv_bfloat162 hp0; hp0.x = h0; hp0.y = h1;
    __nv_bfloat162 hp1; hp1.x = h2; hp1.y = h3;
    *(__nv_bfloat162*)(g_Whi + i)     = hp0;
    *(__nv_bfloat162*)(g_Whi + i + 2) = hp1;
    __nv_bfloat162 lp0, lp1;
    lp0.x = __float2bfloat16_rn(v.x - __bfloat162float(h0));
    lp0.y = __float2bfloat16_rn(v.y - __bfloat162float(h1));
    lp1.x = __float2bfloat16_rn(v.z - __bfloat162float(h2));
    lp1.y = __float2bfloat16_rn(v.w - __bfloat162float(h3));
    *(__nv_bfloat162*)(g_Wlo + i)     = lp0;
    *(__nv_bfloat162*)(g_Wlo + i + 2) = lp1;
}

// ---------------- LSTM gates GEMM (partials) ----------------
__global__ void __launch_bounds__(256) cell_kernel(const float* __restrict__ embedW,
                                                   const float* __restrict__ W_ih,
                                                   const float* __restrict__ W_hh) {
    __shared__ float Ws[32][32];
    __shared__ float Xs[32][64];
    int cg  = blockIdx.x;
    int kc  = blockIdx.y;
    int tid = threadIdx.x;
    int gbase = cg * 32;
    int koff  = (kc & 1) * 256;
    const float* Wmat = (kc < 2) ? W_ih : W_hh;

    int wn = tid & 31;
    int wk = (tid >> 5) << 2;
    const float* wptr = Wmat + (size_t)(gbase + wn) * H_ + koff + wk;

    int xm = tid & 63;
    int xk = (tid >> 6) << 3;
    const float* xrow;
    if (kc < 2) xrow = embedW + (size_t)g_tok[xm] * H_ + koff + xk;
    else        xrow = g_h    + (size_t)xm        * H_ + koff + xk;

    int nt = (tid & 15) * 2;
    int mt = (tid >> 4) * 4;
    float acc[4][2] = {};

    for (int s = 0; s < 8; ++s) {
        float4 wv = *(const float4*)(wptr + s * 32);
        float4 x0 = *(const float4*)(xrow + s * 32);
        float4 x1 = *(const float4*)(xrow + s * 32 + 4);
        __syncthreads();
        Ws[wk + 0][wn] = wv.x; Ws[wk + 1][wn] = wv.y;
        Ws[wk + 2][wn] = wv.z; Ws[wk + 3][wn] = wv.w;
        Xs[xk + 0][xm] = x0.x; Xs[xk + 1][xm] = x0.y;
        Xs[xk + 2][xm] = x0.z; Xs[xk + 3][xm] = x0.w;
        Xs[xk + 4][xm] = x1.x; Xs[xk + 5][xm] = x1.y;
        Xs[xk + 6][xm] = x1.z; Xs[xk + 7][xm] = x1.w;
        __syncthreads();
#pragma unroll
        for (int k = 0; k < 32; ++k) {
            float a0 = Ws[k][nt], a1 = Ws[k][nt + 1];
            float4 b = *(const float4*)&Xs[k][mt];
            acc[0][0] += b.x * a0; acc[0][1] += b.x * a1;
            acc[1][0] += b.y * a0; acc[1][1] += b.y * a1;
            acc[2][0] += b.z * a0; acc[2][1] += b.z * a1;
            acc[3][0] += b.w * a0; acc[3][1] += b.w * a1;
        }
    }
    float* gp = g_gates_part + (size_t)kc * (B_ * 2048);
#pragma unroll
    for (int i = 0; i < 4; ++i)
#pragma unroll
        for (int j = 0; j < 2; ++j)
            gp[(size_t)(mt + i) * 2048 + gbase + nt + j] = acc[i][j];
}

// ---------------- activations + cell/hidden update (+ bf16 split) ----------------
__global__ void update_kernel(const float* __restrict__ b_ih,
                              const float* __restrict__ b_hh) {
    int b = blockIdx.x, col = threadIdx.x;
    float gi = b_ih[col]        + b_hh[col];
    float gf = b_ih[col + 512]  + b_hh[col + 512];
    float gg = b_ih[col + 1024] + b_hh[col + 1024];
    float go = b_ih[col + 1536] + b_hh[col + 1536];
#pragma unroll
    for (int ks = 0; ks < 4; ++ks) {
        const float* p = g_gates_part + (size_t)ks * (B_ * 2048) + (size_t)b * 2048;
        gi += p[col]; gf += p[col + 512]; gg += p[col + 1024]; go += p[col + 1536];
    }
    float i = sigmoidf_(gi), f = sigmoidf_(gf), g = tanhf(gg), o = sigmoidf_(go);
    float c = f * g_c[b * H_ + col] + i * g;
    float h = o * tanhf(c);
    g_c[b * H_ + col] = c;
    g_h[b * H_ + col] = h;
    __nv_bfloat16 hi = __float2bfloat16_rn(h);
    g_Hhi[b * H_ + col] = hi;
    g_Hlo[b * H_ + col] = __float2bfloat16_rn(h - __bfloat162float(hi));
}

// ---------------- HMMA logits GEMM ----------------
// Block: M=256 vocab rows x N=64 batch x K=512, 8 warps (warp = 2 x m16 tiles).
// 3 passes: Whi*Hhi + Whi*Hlo + Wlo*Hhi. H staged in smem, W streamed via LDG.
#define SHH 0
#define SHL 66560           // 64 rows * 520 halfs * 2B
#define WVOFF 133120        // 8*64 float warp partials
#define WIOFF 135168        // 8*64 int
#define SMEMB 137216
#define HSTRIDE 520         // halfwords per H smem row (bank-conflict-free)

__global__ void __launch_bounds__(256) logits_mma_kernel(const float* __restrict__ bias,
                                                         float* __restrict__ out, int t) {
    extern __shared__ char smem[];
    int tid = threadIdx.x;
    int wid = tid >> 5, lane = tid & 31;
    int q = lane & 3, r = lane >> 2;

    // stage H hi/lo into smem, padded rows
    for (int u = tid; u < 4096; u += 256) {
        int row = u >> 6, j = u & 63;
        *(uint4*)(smem + SHH + row * (HSTRIDE * 2) + j * 16) =
            *(const uint4*)(g_Hhi + row * H_ + j * 8);
        *(uint4*)(smem + SHL + row * (HSTRIDE * 2) + j * 16) =
            *(const uint4*)(g_Hlo + row * H_ + j * 8);
    }
    __syncthreads();

    int vb = blockIdx.x * 256 + wid * 32;          // warp vocab base
    const __nv_bfloat16* pAh = g_Whi + (size_t)(vb + r) * H_ + q * 2;
    const __nv_bfloat16* pAl = g_Wlo + (size_t)(vb + r) * H_ + q * 2;

    float acc[2][8][4];
#pragma unroll
    for (int m = 0; m < 2; ++m)
#pragma unroll
        for (int n = 0; n < 8; ++n)
#pragma unroll
            for (int k = 0; k < 4; ++k) acc[m][n][k] = 0.0f;

    for (int ks = 0; ks < 32; ++ks) {
        uint32_t ah[2][4], al[2][4];
#pragma unroll
        for (int m = 0; m < 2; ++m) {
            const __nv_bfloat16* ph = pAh + (size_t)m * 16 * H_ + ks * 16;
            const __nv_bfloat16* pl = pAl + (size_t)m * 16 * H_ + ks * 16;
            ah[m][0] = *(const uint32_t*)(ph);
            ah[m][1] = *(const uint32_t*)(ph + 8 * H_);
            ah[m][2] = *(const uint32_t*)(ph + 8);
            ah[m][3] = *(const uint32_t*)(ph + 8 * H_ + 8);
            al[m][0] = *(const uint32_t*)(pl);
            al[m][1] = *(const uint32_t*)(pl + 8 * H_);
            al[m][2] = *(const uint32_t*)(pl + 8);
            al[m][3] = *(const uint32_t*)(pl + 8 * H_ + 8);
        }
        uint32_t bh[8][2], bl[8][2];
#pragma unroll
        for (int n = 0; n < 8; ++n) {
            int off = (n * 8 + r) * (HSTRIDE * 2) + q * 4 + ks * 32;
            bh[n][0] = *(const uint32_t*)(smem + SHH + off);
            bh[n][1] = *(const uint32_t*)(smem + SHH + off + 16);
            bl[n][0] = *(const uint32_t*)(smem + SHL + off);
            bl[n][1] = *(const uint32_t*)(smem + SHL + off + 16);
        }
#pragma unroll
        for (int m = 0; m < 2; ++m)
#pragma unroll
            for (int n = 0; n < 8; ++n) {
                mma16816(acc[m][n], ah[m], bh[n]);
                mma16816(acc[m][n], ah[m], bl[n]);
                mma16816(acc[m][n], al[m], bh[n]);
            }
    }

    // epilogue: bias + store + per-col argmax (registers)
    float bias_r[2][2];
#pragma unroll
    for (int m = 0; m < 2; ++m) {
        bias_r[m][0] = bias[vb + m * 16 + r];
        bias_r[m][1] = bias[vb + m * 16 + r + 8];
    }
    float bestv[16];
    int   besti[16];
#pragma unroll
    for (int i = 0; i < 16; ++i) { bestv[i] = -3.4e38f; besti[i] = 0; }

#pragma unroll
    for (int m = 0; m < 2; ++m)
#pragma unroll
        for (int n = 0; n < 8; ++n) {
            int v0 = vb + m * 16 + r;
            int c0 = n * 8 + q * 2;
            float o00 = acc[m][n][0] + bias_r[m][0];
            float o01 = acc[m][n][1] + bias_r[m][0];
            float o10 = acc[m][n][2] + bias_r[m][1];
            float o11 = acc[m][n][3] + bias_r[m][1];
            out[((size_t)c0       * T_ + t) * V_ + v0]     = o00;
            out[((size_t)(c0 + 1) * T_ + t) * V_ + v0]     = o01;
            out[((size_t)c0       * T_ + t) * V_ + v0 + 8] = o10;
            out[((size_t)(c0 + 1) * T_ + t) * V_ + v0 + 8] = o11;
            // ascending-v updates with strict > keep first occurrence
            int i0 = n * 2, i1 = n * 2 + 1;
            if (o00 > bestv[i0]) { bestv[i0] = o00; besti[i0] = v0; }
            if (o10 > bestv[i0]) { bestv[i0] = o10; besti[i0] = v0 + 8; }
            if (o01 > bestv[i1]) { bestv[i1] = o01; besti[i1] = v0; }
            if (o11 > bestv[i1]) { bestv[i1] = o11; besti[i1] = v0 + 8; }
        }
    // reduce across row-lanes (r = lane>>2); partners share q so cols match
#pragma unroll
    for (int off = 4; off <= 16; off <<= 1) {
#pragma unroll
        for (int i = 0; i < 16; ++i) {
            float pv = __shfl_xor_sync(0xffffffffu, bestv[i], off);
            int   pi = __shfl_xor_sync(0xffffffffu, besti[i], off);
            if (pv > bestv[i] || (pv == bestv[i] && pi < besti[i])) {
                bestv[i] = pv; besti[i] = pi;
            }
        }
    }
    float* wV = (float*)(smem + WVOFF);
    int*   wI = (int*)(smem + WIOFF);
    if (r == 0) {
#pragma unroll
        for (int i = 0; i < 16; ++i) {
            int c = (i >> 1) * 8 + q * 2 + (i & 1);
            wV[wid * 64 + c] = bestv[i];
            wI[wid * 64 + c] = besti[i];
        }
    }
    __syncthreads();
    if (tid < 64) {
        float best = wV[tid]; int bidx = wI[tid];   // warp 0 = lowest v range
#pragma unroll
        for (int w = 1; w < 8; ++w) {
            float v2 = wV[w * 64 + tid];
            int   i2 = wI[w * 64 + tid];
            if (v2 > best || (v2 == best && i2 < bidx)) { best = v2; bidx = i2; }
        }
        g_amax_val[blockIdx.x * B_ + tid] = best;
        g_amax_idx[blockIdx.x * B_ + tid] = bidx;
    }
}

// ---------------- final argmax over tile partials -> next token ----------------
__global__ void argmax_kernel() {
    int tid = threadIdx.x;
    int row = tid >> 3;
    int j   = tid & 7;
    float bv = -3.4e38f; int bi = 0x7fffffff;
    for (int p = j; p < NTILES; p += 8) {
        float v = g_amax_val[p * B_ + row];
        int  id = g_amax_idx[p * B_ + row];
        if (v > bv || (v == bv && id < bi)) { bv = v; bi = id; }
    }
    for (int off = 4; off > 0; off >>= 1) {
        float ov = __shfl_down_sync(0xffffffffu, bv, off, 8);
        int   oi = __shfl_down_sync(0xffffffffu, bi, off, 8);
        if (ov > bv || (ov == bv && oi < bi)) { bv = ov; bi = oi; }
    }
    if (j == 0) g_tok[row] = bi;
}

// ---------------- launcher ----------------
extern "C" void kernel_launch(void* const* d_in, const int* in_sizes, int n_in,
                              void* d_out, int out_size) {
    const float *features = nullptr, *embedW = nullptr, *W_ih = nullptr, *W_hh = nullptr;
    const float *b_ih = nullptr, *b_hh = nullptr, *linW = nullptr, *linb = nullptr;
    const void  *captions = nullptr;
    for (int i = 0; i < n_in; ++i) {
        int s = in_sizes[i];
        const void* p = d_in[i];
        if (s == 32768)            features = (const float*)p;
        else if (s == 64)          captions = p;
        else if (s == 16384000) {  if (!embedW) embedW = (const float*)p; else linW = (const float*)p; }
        else if (s == 1048576)  {  if (!W_ih)   W_ih   = (const float*)p; else W_hh = (const float*)p; }
        else if (s == 2048)     {  if (!b_ih)   b_ih   = (const float*)p; else b_hh = (const float*)p; }
        else if (s == 32000)       linb = (const float*)p;
    }
    float* out = (float*)d_out;

    static int smem_set = 0;
    if (!smem_set) {
        cudaFuncSetAttribute(logits_mma_kernel,
                             cudaFuncAttributeMaxDynamicSharedMemorySize, SMEMB);
        smem_set = 1;
    }

    convert_w_kernel<<<16000, 256>>>(linW);
    init_kernel<<<B_, H_>>>(features, captions);
    for (int t = 0; t < T_; ++t) {
        cell_kernel<<<dim3(64, 4), 256>>>(embedW, W_ih, W_hh);
        update_kernel<<<B_, H_>>>(b_ih, b_hh);
        logits_mma_kernel<<<NBLOCKS, 256, SMEMB>>>(linb, out, t);
        if (t < T_ - 1) argmax_kernel<<<1, 512>>>();
    }
}